// round 3
// baseline (speedup 1.0000x reference)
#include <cuda_runtime.h>
#include <cuda_bf16.h>
#include <mma.h>
#include <cstdint>

using namespace nvcuda;

// ---------------------------------------------------------------------------
// Problem constants
// ---------------------------------------------------------------------------
#define BATCH   32
#define CH      1280
#define HW      256                 // 16*16
#define NROWS   8192                // BATCH*HW
#define HID     20480
#define KDIM    1280
#define TOPK    32
#define NCAND   48                  // pass-1 candidates per row

#define SPARSE_ELEMS  (167772160u)  // NROWS * HID
#define RECON_ELEMS   (10485760u)   // BATCH*CH*HW

// ---------------------------------------------------------------------------
// Device scratch (__device__ globals: the sanctioned no-alloc workaround)
// ---------------------------------------------------------------------------
__device__ float          g_enc [(size_t)NROWS * HID];   // raw encoder pre-act (no bias/relu)
__device__ float          g_WdT [(size_t)HID * CH];      // W_dec transposed [HID][CH]
__device__ float          g_xf32[(size_t)NROWS * KDIM];  // x_flat fp32 [N][C]
__device__ __nv_bfloat16  g_xbf [(size_t)NROWS * KDIM];  // x_flat bf16
__device__ __nv_bfloat16  g_Wbf [(size_t)HID * KDIM];    // W_enc bf16
__device__ float          g_cval[NROWS * NCAND];
__device__ int            g_cidx[NROWS * NCAND];
__device__ float          g_vals[NROWS * TOPK];
__device__ int            g_idx [NROWS * TOPK];

// ---------------------------------------------------------------------------
// 1a) x [B, C, HW] -> x_flat [n = b*HW+hw][c]  (fp32 + bf16 copies)
// ---------------------------------------------------------------------------
__global__ __launch_bounds__(256) void k_cvt_x(const float* __restrict__ x)
{
    __shared__ float t[32][33];
    const int hx = blockIdx.x * 32;          // hw tile
    const int cy = blockIdx.y * 32;          // c tile
    const int b  = blockIdx.z;
    const int tx = threadIdx.x, ty = threadIdx.y;
#pragma unroll
    for (int i = 0; i < 32; i += 8)
        t[ty + i][tx] = x[(size_t)b * CH * HW + (size_t)(cy + ty + i) * HW + hx + tx];
    __syncthreads();
#pragma unroll
    for (int i = 0; i < 32; i += 8) {
        float v = t[tx][ty + i];
        size_t o = (size_t)(b * HW + hx + ty + i) * KDIM + cy + tx;
        g_xf32[o] = v;
        g_xbf [o] = __float2bfloat16(v);
    }
}

// ---------------------------------------------------------------------------
// 1b) W_enc fp32 -> bf16
// ---------------------------------------------------------------------------
__global__ __launch_bounds__(256) void k_cvt_w(const float* __restrict__ W)
{
    size_t i = ((size_t)blockIdx.x * 256 + threadIdx.x) * 4;
    float4 v = *(const float4*)(W + i);
    __nv_bfloat162 lo = __floats2bfloat162_rn(v.x, v.y);
    __nv_bfloat162 hi = __floats2bfloat162_rn(v.z, v.w);
    uint2 p; p.x = *(uint32_t*)&lo; p.y = *(uint32_t*)&hi;
    *(uint2*)(g_Wbf + i) = p;
}

// ---------------------------------------------------------------------------
// 1c) Transpose W_dec [CH, HID] -> g_WdT [HID, CH]
// ---------------------------------------------------------------------------
__global__ __launch_bounds__(256) void k_transpose(const float* __restrict__ Wd)
{
    __shared__ float t[32][33];
    int hx = blockIdx.x * 32, cy = blockIdx.y * 32;
    int tx = threadIdx.x, ty = threadIdx.y;
#pragma unroll
    for (int i = 0; i < 32; i += 8)
        t[ty + i][tx] = Wd[(size_t)(cy + ty + i) * HID + hx + tx];
    __syncthreads();
#pragma unroll
    for (int i = 0; i < 32; i += 8)
        g_WdT[(size_t)(hx + ty + i) * CH + cy + tx] = t[tx][ty + i];
}

// ---------------------------------------------------------------------------
// 2) Pass-1 encoder GEMM (bf16 wmma, fp32 accum), raw output (no bias/relu).
//    C tile 128x128, BK=64, 256 threads = 8 warps (4 x 2), warp tile 32x64.
// ---------------------------------------------------------------------------
#define GBK 64
#define LDA 72   // 64 + 8 pad (bf16 elems; 16B-aligned rows)

__global__ __launch_bounds__(256) void k_enc_wmma()
{
    __shared__ __nv_bfloat16 As[128][LDA];
    __shared__ __nv_bfloat16 Bs[128][LDA];

    const int tid = threadIdx.x;
    const int wid = tid >> 5;
    const int hn0 = blockIdx.x * 128;
    const int bm0 = blockIdx.y * 128;
    const int wm  = (wid & 3) * 32;     // warp m-offset
    const int wn  = (wid >> 2) * 64;    // warp n-offset

    wmma::fragment<wmma::accumulator, 16, 16, 16, float> acc[2][4];
#pragma unroll
    for (int i = 0; i < 2; i++)
#pragma unroll
        for (int j = 0; j < 4; j++) wmma::fill_fragment(acc[i][j], 0.f);

    for (int k0 = 0; k0 < KDIM; k0 += GBK) {
#pragma unroll
        for (int p = 0; p < 4; p++) {
            int idx = tid + p * 256;
            int r = idx >> 3, c = (idx & 7) * 8;
            *(uint4*)&As[r][c] = *(const uint4*)(g_xbf + (size_t)(bm0 + r) * KDIM + k0 + c);
            *(uint4*)&Bs[r][c] = *(const uint4*)(g_Wbf + (size_t)(hn0 + r) * KDIM + k0 + c);
        }
        __syncthreads();

#pragma unroll
        for (int kk = 0; kk < GBK; kk += 16) {
            wmma::fragment<wmma::matrix_a, 16, 16, 16, __nv_bfloat16, wmma::row_major> af[2];
            wmma::fragment<wmma::matrix_b, 16, 16, 16, __nv_bfloat16, wmma::col_major> bf[4];
#pragma unroll
            for (int i = 0; i < 2; i++)
                wmma::load_matrix_sync(af[i], &As[wm + i * 16][kk], LDA);
#pragma unroll
            for (int j = 0; j < 4; j++)
                wmma::load_matrix_sync(bf[j], &Bs[wn + j * 16][kk], LDA);
#pragma unroll
            for (int i = 0; i < 2; i++)
#pragma unroll
                for (int j = 0; j < 4; j++)
                    wmma::mma_sync(acc[i][j], af[i], bf[j], acc[i][j]);
        }
        __syncthreads();
    }

#pragma unroll
    for (int i = 0; i < 2; i++)
#pragma unroll
        for (int j = 0; j < 4; j++)
            wmma::store_matrix_sync(
                g_enc + (size_t)(bm0 + wm + i * 16) * HID + hn0 + wn + j * 16,
                acc[i][j], HID, wmma::mem_row_major);
}

// ---------------------------------------------------------------------------
// 3) Top-NCAND candidates per row (on bias+relu'd pass-1 values).
//    One block (512 thr) per row; row cached in dynamic smem; iterative argmax.
// ---------------------------------------------------------------------------
__global__ __launch_bounds__(512) void k_topk(const float* __restrict__ b_enc)
{
    extern __shared__ float srow[];       // HID floats (80 KB)
    __shared__ float tval[512];
    __shared__ int   targ[512];
    __shared__ float wmax[16];
    __shared__ int   warg[16];
    __shared__ int   s_ga;

    const int tid = threadIdx.x;
    const int row = blockIdx.x;
    const float* r = g_enc + (size_t)row * HID;

    float lmax = -1.f; int larg = 0;
#pragma unroll
    for (int j = 0; j < HID / 512; j++) {
        int i = j * 512 + tid;
        float v = fmaxf(r[i] + b_enc[i], 0.f);
        srow[i] = v;
        if (v > lmax) { lmax = v; larg = i; }
    }
    tval[tid] = lmax; targ[tid] = larg;
    __syncthreads();

    for (int it = 0; it < NCAND; ++it) {
        float v = tval[tid]; int a = targ[tid];
#pragma unroll
        for (int off = 16; off; off >>= 1) {
            float ov = __shfl_down_sync(0xffffffffu, v, off);
            int   oa = __shfl_down_sync(0xffffffffu, a, off);
            if (ov > v || (ov == v && oa < a)) { v = ov; a = oa; }
        }
        if ((tid & 31) == 0) { wmax[tid >> 5] = v; warg[tid >> 5] = a; }
        __syncthreads();
        if (tid < 32) {
            v = (tid < 16) ? wmax[tid] : -2.f;
            a = (tid < 16) ? warg[tid] : (1 << 30);
#pragma unroll
            for (int off = 8; off; off >>= 1) {
                float ov = __shfl_down_sync(0xffffffffu, v, off);
                int   oa = __shfl_down_sync(0xffffffffu, a, off);
                if (ov > v || (ov == v && oa < a)) { v = ov; a = oa; }
            }
            if (tid == 0) {
                s_ga = a;
                g_cval[row * NCAND + it] = v;
                g_cidx[row * NCAND + it] = a;
            }
        }
        __syncthreads();
        int ga = s_ga;
        if (tid == (ga & 511)) {
            srow[ga] = -1.f;
            float lm = -1.f; int la = 0;
#pragma unroll
            for (int j = 0; j < HID / 512; j++) {
                int i = j * 512 + tid;
                float vv = srow[i];
                if (vv > lm) { lm = vv; la = i; }
            }
            tval[tid] = lm; targ[tid] = la;
        }
        __syncthreads();
    }
}

// ---------------------------------------------------------------------------
// 4) Refinement: recompute the NCAND candidate dots per row in fp64, then
//    exact top-32 among candidates (rank by value desc, index asc).
//    Writes sparse values + (g_vals, g_idx) for the decoder.
// ---------------------------------------------------------------------------
__global__ __launch_bounds__(256) void k_refine(
    const float* __restrict__ W_enc,
    const float* __restrict__ b_enc,
    float* __restrict__ sparse_out)
{
    __shared__ float sx[KDIM];
    __shared__ float rv[NCAND];
    __shared__ int   ri[NCAND];

    const int row  = blockIdx.x;
    const int tid  = threadIdx.x;
    const int wid  = tid >> 5;
    const int lane = tid & 31;

    for (int i = tid; i < KDIM; i += 256)
        sx[i] = g_xf32[(size_t)row * KDIM + i];
    __syncthreads();

    for (int c = wid; c < NCAND; c += 8) {
        const int h = g_cidx[row * NCAND + c];
        const float* w = W_enc + (size_t)h * KDIM;
        double acc = 0.0;
#pragma unroll 8
        for (int j = lane; j < KDIM; j += 32)
            acc += (double)sx[j] * (double)w[j];
#pragma unroll
        for (int off = 16; off; off >>= 1)
            acc += __shfl_down_sync(0xffffffffu, acc, off);
        if (lane == 0) {
            rv[c] = fmaxf((float)(acc + (double)b_enc[h]), 0.f);
            ri[c] = h;
        }
    }
    __syncthreads();

    if (tid < NCAND) {
        float v = rv[tid]; int h = ri[tid];
        int rank = 0;
#pragma unroll
        for (int j = 0; j < NCAND; j++)
            rank += (rv[j] > v) || (rv[j] == v && ri[j] < h);
        if (rank < TOPK) {
            sparse_out[(size_t)row * HID + h] = v;
            g_vals[row * TOPK + rank] = v;
            g_idx [row * TOPK + rank] = h;
        }
    }
}

// ---------------------------------------------------------------------------
// 5) Sparse decoder: dec[n,c] = b_dec[c] + sum_k vals[k]*WdT[idx[k], c]
// ---------------------------------------------------------------------------
__global__ __launch_bounds__(320) void k_decoder(
    const float* __restrict__ b_dec, float* __restrict__ out)
{
    __shared__ float sv[TOPK];
    __shared__ int   si[TOPK];
    const int row = blockIdx.x;
    const int tid = threadIdx.x;
    if (tid < TOPK) {
        sv[tid] = g_vals[row * TOPK + tid];
        si[tid] = g_idx [row * TOPK + tid];
    }
    __syncthreads();

    const int c0 = tid * 4;
    float4 acc = *(const float4*)(b_dec + c0);
#pragma unroll 8
    for (int k = 0; k < TOPK; k++) {
        float v = sv[k];
        float4 w = *(const float4*)(g_WdT + (size_t)si[k] * CH + c0);
        acc.x += v * w.x; acc.y += v * w.y;
        acc.z += v * w.z; acc.w += v * w.w;
    }
    const size_t b  = (size_t)(row >> 8);
    const int    hw = row & 255;
    float* o = out + SPARSE_ELEMS + b * CH * HW + hw;
    o[(size_t)(c0 + 0) * HW] = acc.x;
    o[(size_t)(c0 + 1) * HW] = acc.y;
    o[(size_t)(c0 + 2) * HW] = acc.z;
    o[(size_t)(c0 + 3) * HW] = acc.w;
}

// ---------------------------------------------------------------------------
// Launch
// ---------------------------------------------------------------------------
extern "C" void kernel_launch(void* const* d_in, const int* in_sizes, int n_in,
                              void* d_out, int out_size)
{
    const float* x     = (const float*)d_in[0];
    const float* W_enc = (const float*)d_in[1];
    const float* b_enc = (const float*)d_in[2];
    const float* W_dec = (const float*)d_in[3];
    const float* b_dec = (const float*)d_in[4];
    float* out = (float*)d_out;

    // zero the sparse region (memset node in the graph)
    cudaMemsetAsync(out, 0, (size_t)SPARSE_ELEMS * sizeof(float), 0);

    // layout conversions
    {
        dim3 grid(HW / 32, CH / 32, BATCH), block(32, 8);
        k_cvt_x<<<grid, block>>>(x);
    }
    k_cvt_w<<<(HID * KDIM / 4 + 255) / 256, 256>>>(W_enc);
    {
        dim3 grid(HID / 32, CH / 32), block(32, 8);
        k_transpose<<<grid, block>>>(W_dec);
    }

    // pass-1 encoder GEMM (bf16 tensor cores)
    {
        dim3 grid(HID / 128, NROWS / 128);   // (160, 64)
        k_enc_wmma<<<grid, 256>>>();
    }

    // candidate top-48 (needs >48KB dynamic smem)
    static int smem_set = 0;
    if (!smem_set) {
        cudaFuncSetAttribute(k_topk, cudaFuncAttributeMaxDynamicSharedMemorySize,
                             HID * (int)sizeof(float));
        smem_set = 1;
    }
    k_topk<<<NROWS, 512, HID * sizeof(float)>>>(b_enc);

    // fp64 refinement + exact top-32 + sparse scatter
    k_refine<<<NROWS, 256>>>(W_enc, b_enc, out);

    // sparse decoder -> reconstructed region
    k_decoder<<<NROWS, 320>>>(b_dec, out);

    (void)in_sizes; (void)n_in; (void)out_size;
}

// round 5
// speedup vs baseline: 1.2423x; 1.2423x over previous
#include <cuda_runtime.h>
#include <cuda_bf16.h>
#include <mma.h>
#include <cstdint>

using namespace nvcuda;

// ---------------------------------------------------------------------------
// Problem constants
// ---------------------------------------------------------------------------
#define BATCH   32
#define CH      1280
#define HW      256
#define NROWS   8192                // BATCH*HW
#define HID     20480
#define KDIM    1280
#define TOPK    32
#define NCAND   48

#define SPARSE_ELEMS  (167772160u)  // NROWS * HID
#define RECON_ELEMS   (10485760u)

// ---------------------------------------------------------------------------
// Device scratch
// ---------------------------------------------------------------------------
__device__ __nv_bfloat16  g_enc [(size_t)NROWS * HID];   // bias+relu'd acts (bf16)
__device__ float          g_WdT [(size_t)HID * CH];
__device__ float          g_xf32[(size_t)NROWS * KDIM];
__device__ __nv_bfloat16  g_xbf [(size_t)NROWS * KDIM];
__device__ __nv_bfloat16  g_Wbf [(size_t)HID * KDIM];
__device__ int            g_cidx[NROWS * NCAND];
__device__ float          g_vals[NROWS * TOPK];
__device__ int            g_idx [NROWS * TOPK];

// ---------------------------------------------------------------------------
// cp.async helpers (Ampere+ base ISA; no tcgen05 anywhere in this file)
// ---------------------------------------------------------------------------
__device__ __forceinline__ uint32_t smem_u32(const void* p) {
    uint32_t a;
    asm("{ .reg .u64 t; cvta.to.shared.u64 t, %1; cvt.u32.u64 %0, t; }" : "=r"(a) : "l"(p));
    return a;
}
__device__ __forceinline__ void cp8(uint32_t dst, const void* src) {
    asm volatile("cp.async.ca.shared.global [%0], [%1], 8;" :: "r"(dst), "l"(src));
}
#define CP_COMMIT()  asm volatile("cp.async.commit_group;" ::: "memory")
#define CP_WAIT1()   asm volatile("cp.async.wait_group 1;" ::: "memory")
#define CP_WAIT0()   asm volatile("cp.async.wait_group 0;" ::: "memory")

// ---------------------------------------------------------------------------
// 1a) x [B, C, HW] -> x_flat [n][c] (fp32 + bf16)
// ---------------------------------------------------------------------------
__global__ __launch_bounds__(256) void k_cvt_x(const float* __restrict__ x)
{
    __shared__ float t[32][33];
    const int hx = blockIdx.x * 32, cy = blockIdx.y * 32, b = blockIdx.z;
    const int tx = threadIdx.x, ty = threadIdx.y;
#pragma unroll
    for (int i = 0; i < 32; i += 8)
        t[ty + i][tx] = x[(size_t)b * CH * HW + (size_t)(cy + ty + i) * HW + hx + tx];
    __syncthreads();
#pragma unroll
    for (int i = 0; i < 32; i += 8) {
        float v = t[tx][ty + i];
        size_t o = (size_t)(b * HW + hx + ty + i) * KDIM + cy + tx;
        g_xf32[o] = v;
        g_xbf [o] = __float2bfloat16(v);
    }
}

// 1b) W_enc fp32 -> bf16
__global__ __launch_bounds__(256) void k_cvt_w(const float* __restrict__ W)
{
    size_t i = ((size_t)blockIdx.x * 256 + threadIdx.x) * 4;
    float4 v = *(const float4*)(W + i);
    __nv_bfloat162 lo = __floats2bfloat162_rn(v.x, v.y);
    __nv_bfloat162 hi = __floats2bfloat162_rn(v.z, v.w);
    uint2 p; p.x = *(uint32_t*)&lo; p.y = *(uint32_t*)&hi;
    *(uint2*)(g_Wbf + i) = p;
}

// 1c) W_dec [CH, HID] -> g_WdT [HID, CH]
__global__ __launch_bounds__(256) void k_transpose(const float* __restrict__ Wd)
{
    __shared__ float t[32][33];
    int hx = blockIdx.x * 32, cy = blockIdx.y * 32;
    int tx = threadIdx.x, ty = threadIdx.y;
#pragma unroll
    for (int i = 0; i < 32; i += 8)
        t[ty + i][tx] = Wd[(size_t)(cy + ty + i) * HID + hx + tx];
    __syncthreads();
#pragma unroll
    for (int i = 0; i < 32; i += 8)
        g_WdT[(size_t)(hx + ty + i) * CH + cy + tx] = t[tx][ty + i];
}

// ---------------------------------------------------------------------------
// 2) Encoder GEMM: wmma bf16, block tile 128(M) x 256(N), BK=64, 8 warps
//    (2x4), warp tile 64x64 (4x4 fragments). cp.async double-buffered.
//    Epilogue: bias + relu -> bf16 store to g_enc.
// ---------------------------------------------------------------------------
#define TM 128
#define TN 256
#define TK 64
#define NCHUNK (KDIM / TK)          // 20
#define LDAB 72                     // bf16 elems per row (64 + 8 pad; 144B)

#define SM_BIAS  0                  // 256 floats = 1024 B
#define SM_A0    1024               // 128*144 = 18432
#define SM_A1    (SM_A0 + 18432)
#define SM_B0    (SM_A1 + 18432)    // 256*144 = 36864
#define SM_B1    (SM_B0 + 36864)
#define SM_GEMM_TOTAL (SM_B1 + 36864)   // 111616 B

__global__ __launch_bounds__(256, 1) void k_enc_wmma2(const float* __restrict__ b_enc)
{
    extern __shared__ char smem[];
    const uint32_t sb = smem_u32(smem);
    const int tid  = threadIdx.x;
    const int wid  = tid >> 5;
    const int lane = tid & 31;
    const int hn0  = blockIdx.x * TN;
    const int bm0  = blockIdx.y * TM;
    const int wm   = (wid & 1) * 64;
    const int wn   = (wid >> 1) * 64;

    float* bias = (float*)(smem + SM_BIAS);
    if (tid < 256) bias[tid] = b_enc[hn0 + tid];

    wmma::fragment<wmma::accumulator, 16, 16, 16, float> acc[4][4];
#pragma unroll
    for (int i = 0; i < 4; i++)
#pragma unroll
        for (int j = 0; j < 4; j++) wmma::fill_fragment(acc[i][j], 0.f);

    // async loader for one K-chunk into buffer buf
    auto issue = [&](int c, int buf) {
        const int k0 = c * TK;
        const uint32_t sA = sb + (buf ? SM_A1 : SM_A0);
        const uint32_t sB = sb + (buf ? SM_B1 : SM_B0);
        // A: 128 rows x 128B = 2048 x 8B
#pragma unroll
        for (int p = 0; p < 8; ++p) {
            int t = tid + p * 256;
            int r = t >> 4, c8 = t & 15;
            cp8(sA + (uint32_t)(r * 144 + c8 * 8),
                g_xbf + (size_t)(bm0 + r) * KDIM + k0 + c8 * 4);
        }
        // B: 256 rows x 128B = 4096 x 8B
#pragma unroll
        for (int p = 0; p < 16; ++p) {
            int t = tid + p * 256;
            int r = t >> 4, c8 = t & 15;
            cp8(sB + (uint32_t)(r * 144 + c8 * 8),
                g_Wbf + (size_t)(hn0 + r) * KDIM + k0 + c8 * 4);
        }
    };

    issue(0, 0);
    CP_COMMIT();

    for (int c = 0; c < NCHUNK; ++c) {
        const int buf = c & 1;
        if (c + 1 < NCHUNK) {
            issue(c + 1, buf ^ 1);
            CP_COMMIT();
            CP_WAIT1();
        } else {
            CP_WAIT0();
        }
        __syncthreads();

        const __nv_bfloat16* A = (const __nv_bfloat16*)(smem + (buf ? SM_A1 : SM_A0));
        const __nv_bfloat16* B = (const __nv_bfloat16*)(smem + (buf ? SM_B1 : SM_B0));
#pragma unroll
        for (int kk = 0; kk < TK; kk += 16) {
            wmma::fragment<wmma::matrix_a, 16, 16, 16, __nv_bfloat16, wmma::row_major> af[4];
            wmma::fragment<wmma::matrix_b, 16, 16, 16, __nv_bfloat16, wmma::col_major> bf[4];
#pragma unroll
            for (int i = 0; i < 4; i++)
                wmma::load_matrix_sync(af[i], A + (wm + i * 16) * LDAB + kk, LDAB);
#pragma unroll
            for (int j = 0; j < 4; j++)
                wmma::load_matrix_sync(bf[j], B + (wn + j * 16) * LDAB + kk, LDAB);
#pragma unroll
            for (int i = 0; i < 4; i++)
#pragma unroll
                for (int j = 0; j < 4; j++)
                    wmma::mma_sync(acc[i][j], af[i], bf[j], acc[i][j]);
        }
        __syncthreads();
    }

    // epilogue: stage each 16x16 frag in smem, bias+relu, bf16 store
    float* stage = (float*)(smem + SM_A0 + wid * 1280);   // 16x20 fp32
    const int rr = lane >> 1;
    const int cc = (lane & 1) * 8;
#pragma unroll
    for (int i = 0; i < 4; i++)
#pragma unroll
        for (int j = 0; j < 4; j++) {
            wmma::store_matrix_sync(stage, acc[i][j], 20, wmma::mem_row_major);
            __syncwarp();
            uint32_t pk[4];
#pragma unroll
            for (int q = 0; q < 4; ++q) {
                float f0 = fmaxf(stage[rr * 20 + cc + 2*q]     + bias[wn + j*16 + cc + 2*q],     0.f);
                float f1 = fmaxf(stage[rr * 20 + cc + 2*q + 1] + bias[wn + j*16 + cc + 2*q + 1], 0.f);
                __nv_bfloat162 h = __floats2bfloat162_rn(f0, f1);
                pk[q] = *(uint32_t*)&h;
            }
            *(uint4*)(g_enc + (size_t)(bm0 + wm + i*16 + rr) * HID + hn0 + wn + j*16 + cc)
                = *(uint4*)pk;
            __syncwarp();
        }
}

// ---------------------------------------------------------------------------
// 3) Radix-select top-NCAND per row on bf16 bit keys (values >= 0, so bit
//    pattern order == value order). Histogram (key = bits>>4, 4096 bins,
//    floored at 0.5f), suffix-scan threshold, collect, O(m^2) rank.
// ---------------------------------------------------------------------------
#define SELCAP 512
#define FLOORKEY 0x3F0u             // bf16 bits of 0.5f >> 4

__global__ __launch_bounds__(512) void k_select()
{
    extern __shared__ unsigned short srow16[];   // HID ushort = 40 KB
    __shared__ unsigned hist[4096];
    __shared__ int ss[512];
    __shared__ unsigned short cv[SELCAP];
    __shared__ int ci[SELCAP];
    __shared__ int s_cnt, s_bstar;

    const int tid = threadIdx.x;
    const int row = blockIdx.x;
    const unsigned short* r = (const unsigned short*)(g_enc + (size_t)row * HID);

#pragma unroll
    for (int j = 0; j < 8; ++j) hist[tid * 8 + j] = 0;
    if (tid == 0) { s_cnt = 0; s_bstar = (int)FLOORKEY; }
    if (tid < NCAND) g_cidx[row * NCAND + tid] = 0;
    __syncthreads();

    // pass 0: vector load, stash, histogram
#pragma unroll
    for (int j = 0; j < 5; ++j) {                 // 5 * 512 * 8 = 20480
        int i8 = (j * 512 + tid) * 8;
        uint4 v = *(const uint4*)(r + i8);
        *(uint4*)(srow16 + i8) = v;
        unsigned short e[8];
        *(uint4*)e = v;
#pragma unroll
        for (int q = 0; q < 8; ++q) {
            unsigned key = (unsigned)e[q] >> 4;
            if (key >= FLOORKEY) atomicAdd(&hist[key], 1u);
        }
    }
    __syncthreads();

    // suffix scan over 512 segments of 8 bins
    {
        int s = 0;
#pragma unroll
        for (int j = 0; j < 8; ++j) s += (int)hist[tid * 8 + j];
        ss[tid] = s;
        __syncthreads();
        for (int off = 1; off < 512; off <<= 1) {
            int v = (tid + off < 512) ? ss[tid + off] : 0;
            __syncthreads();
            ss[tid] += v;
            __syncthreads();
        }
        int above = (tid == 511) ? 0 : ss[tid + 1];
        if (ss[tid] >= NCAND && above < NCAND) {
            int cum = above;
            for (int i = 7; i >= 0; --i) {
                cum += (int)hist[tid * 8 + i];
                if (cum >= NCAND) { s_bstar = tid * 8 + i; break; }
            }
        }
    }
    __syncthreads();
    const unsigned bstar = (unsigned)s_bstar;

    // pass 1: collect candidates (key >= bstar)
#pragma unroll
    for (int j = 0; j < 5; ++j) {
        int i8 = (j * 512 + tid) * 8;
        unsigned short e[8];
        *(uint4*)e = *(uint4*)(srow16 + i8);
#pragma unroll
        for (int q = 0; q < 8; ++q) {
            if (((unsigned)e[q] >> 4) >= bstar) {
                int p = atomicAdd(&s_cnt, 1);
                if (p < SELCAP) { cv[p] = e[q]; ci[p] = i8 + q; }
            }
        }
    }
    __syncthreads();
    const int m = min(s_cnt, SELCAP);

    // pass 2: rank among collected (bf16 bits desc, idx asc)
    if (tid < m) {
        unsigned v = cv[tid]; int h = ci[tid];
        int rank = 0;
        for (int j = 0; j < m; ++j) {
            unsigned vj = cv[j];
            rank += (vj > v) || (vj == v && ci[j] < h);
        }
        if (rank < NCAND) g_cidx[row * NCAND + rank] = h;
    }
}

// ---------------------------------------------------------------------------
// 4) fp64 refinement + exact top-32 + sparse scatter
// ---------------------------------------------------------------------------
__global__ __launch_bounds__(256) void k_refine(
    const float* __restrict__ W_enc,
    const float* __restrict__ b_enc,
    float* __restrict__ sparse_out)
{
    __shared__ float sx[KDIM];
    __shared__ float rv[NCAND];
    __shared__ int   ri[NCAND];

    const int row = blockIdx.x, tid = threadIdx.x;
    const int wid = tid >> 5, lane = tid & 31;

    for (int i = tid; i < KDIM; i += 256)
        sx[i] = g_xf32[(size_t)row * KDIM + i];
    __syncthreads();

    for (int c = wid; c < NCAND; c += 8) {
        const int h = g_cidx[row * NCAND + c];
        const float* w = W_enc + (size_t)h * KDIM;
        double acc = 0.0;
#pragma unroll 8
        for (int j = lane; j < KDIM; j += 32)
            acc += (double)sx[j] * (double)w[j];
#pragma unroll
        for (int off = 16; off; off >>= 1)
            acc += __shfl_down_sync(0xffffffffu, acc, off);
        if (lane == 0) {
            rv[c] = fmaxf((float)(acc + (double)b_enc[h]), 0.f);
            ri[c] = h;
        }
    }
    __syncthreads();

    if (tid < NCAND) {
        float v = rv[tid]; int h = ri[tid];
        int rank = 0;
#pragma unroll
        for (int j = 0; j < NCAND; ++j)
            rank += (rv[j] > v) || (rv[j] == v && ri[j] < h);
        if (rank < TOPK) {
            sparse_out[(size_t)row * HID + h] = v;
            g_vals[row * TOPK + rank] = v;
            g_idx [row * TOPK + rank] = h;
        }
    }
}

// ---------------------------------------------------------------------------
// 5) Sparse decoder
// ---------------------------------------------------------------------------
__global__ __launch_bounds__(320) void k_decoder(
    const float* __restrict__ b_dec, float* __restrict__ out)
{
    __shared__ float sv[TOPK];
    __shared__ int   si[TOPK];
    const int row = blockIdx.x, tid = threadIdx.x;
    if (tid < TOPK) {
        sv[tid] = g_vals[row * TOPK + tid];
        si[tid] = g_idx [row * TOPK + tid];
    }
    __syncthreads();

    const int c0 = tid * 4;
    float4 acc = *(const float4*)(b_dec + c0);
#pragma unroll 8
    for (int k = 0; k < TOPK; ++k) {
        float v = sv[k];
        float4 w = *(const float4*)(g_WdT + (size_t)si[k] * CH + c0);
        acc.x += v * w.x; acc.y += v * w.y;
        acc.z += v * w.z; acc.w += v * w.w;
    }
    const size_t b  = (size_t)(row >> 8);
    const int    hw = row & 255;
    float* o = out + SPARSE_ELEMS + b * CH * HW + hw;
    o[(size_t)(c0 + 0) * HW] = acc.x;
    o[(size_t)(c0 + 1) * HW] = acc.y;
    o[(size_t)(c0 + 2) * HW] = acc.z;
    o[(size_t)(c0 + 3) * HW] = acc.w;
}

// ---------------------------------------------------------------------------
// Launch
// ---------------------------------------------------------------------------
extern "C" void kernel_launch(void* const* d_in, const int* in_sizes, int n_in,
                              void* d_out, int out_size)
{
    const float* x     = (const float*)d_in[0];
    const float* W_enc = (const float*)d_in[1];
    const float* b_enc = (const float*)d_in[2];
    const float* W_dec = (const float*)d_in[3];
    const float* b_dec = (const float*)d_in[4];
    float* out = (float*)d_out;

    static int attr_set = 0;
    if (!attr_set) {
        cudaFuncSetAttribute(k_enc_wmma2, cudaFuncAttributeMaxDynamicSharedMemorySize,
                             SM_GEMM_TOTAL);
        cudaFuncSetAttribute(k_select, cudaFuncAttributeMaxDynamicSharedMemorySize,
                             HID * (int)sizeof(unsigned short));
        attr_set = 1;
    }

    cudaMemsetAsync(out, 0, (size_t)SPARSE_ELEMS * sizeof(float), 0);

    { dim3 g(HW / 32, CH / 32, BATCH), b(32, 8); k_cvt_x<<<g, b>>>(x); }
    k_cvt_w<<<(HID * KDIM / 4 + 255) / 256, 256>>>(W_enc);
    { dim3 g(HID / 32, CH / 32), b(32, 8); k_transpose<<<g, b>>>(W_dec); }

    { dim3 g(HID / TN, NROWS / TM); k_enc_wmma2<<<g, 256, SM_GEMM_TOTAL>>>(b_enc); }

    k_select<<<NROWS, 512, HID * sizeof(unsigned short)>>>();
    k_refine<<<NROWS, 256>>>(W_enc, b_enc, out);
    k_decoder<<<NROWS, 320>>>(b_dec, out);

    (void)in_sizes; (void)n_in; (void)out_size;
}